// round 4
// baseline (speedup 1.0000x reference)
#include <cuda_runtime.h>
#include <cuda_bf16.h>

// ---------------------------------------------------------------------------
// HyperbolicGraphPooling: out[g] = sum_{n: batch[n]==g} sigmoid(f[n]·W+b) * f[n]
// N=500000, C=256, 2048 graphs, batch int32 sorted ascending.
// R4 == R3 resubmit (R3 run died with "system not yet initialized" — infra
// error before kernel entry). Unroll x2, prefetch distance 2 (4 LDG.128 in
// flight/warp), interleaved shfl reductions, __ldcs streaming loads.
// HBM-bound, target ~77 us.
// ---------------------------------------------------------------------------

#define CHANNELS 256
#define THREADS  256

__global__ void hgp_zero_kernel(float4* __restrict__ out, int n4) {
    int i = blockIdx.x * blockDim.x + threadIdx.x;
    if (i < n4) out[i] = make_float4(0.f, 0.f, 0.f, 0.f);
}

__device__ __forceinline__ void flush_seg(float* __restrict__ out,
                                          int seg, int num_segs, int lane,
                                          const float4& a0, const float4& a1) {
    if (seg < 0 || seg >= num_segs) return;   // defensive
    float* p0 = out + (size_t)seg * CHANNELS + 4 * lane;
    float* p1 = p0 + 128;
    atomicAdd(p0 + 0, a0.x);
    atomicAdd(p0 + 1, a0.y);
    atomicAdd(p0 + 2, a0.z);
    atomicAdd(p0 + 3, a0.w);
    atomicAdd(p1 + 0, a1.x);
    atomicAdd(p1 + 1, a1.y);
    atomicAdd(p1 + 2, a1.z);
    atomicAdd(p1 + 3, a1.w);
}

__device__ __forceinline__ float dot8(const float4& f0, const float4& f1,
                                      const float4& w0, const float4& w1) {
    return f0.x * w0.x + f0.y * w0.y + f0.z * w0.z + f0.w * w0.w
         + f1.x * w1.x + f1.y * w1.y + f1.z * w1.z + f1.w * w1.w;
}

__device__ __forceinline__ void acc8(float4& a0, float4& a1,
                                     const float4& f0, const float4& f1, float w) {
    a0.x += f0.x * w; a0.y += f0.y * w; a0.z += f0.z * w; a0.w += f0.w * w;
    a1.x += f1.x * w; a1.y += f1.y * w; a1.z += f1.z * w; a1.w += f1.w * w;
}

__global__ __launch_bounds__(THREADS)
void hgp_pool_kernel(const float* __restrict__ feat,
                     const int* __restrict__ batch,
                     const float* __restrict__ W,
                     const float* __restrict__ b,
                     float* __restrict__ out,
                     int N, int num_segs) {
    const int lane        = threadIdx.x & 31;
    const int warp_global = (blockIdx.x * blockDim.x + threadIdx.x) >> 5;
    const int total_warps = (gridDim.x * blockDim.x) >> 5;

    const int per = (N + total_warps - 1) / total_warps;
    const int n0  = warp_global * per;
    const int n1  = (n0 + per < N) ? (n0 + per) : N;
    if (n0 >= n1) return;
    const int last = n1 - 1;

    const float4 w0 = *reinterpret_cast<const float4*>(W + 4 * lane);
    const float4 w1 = *reinterpret_cast<const float4*>(W + 128 + 4 * lane);
    const float bias = b[0];

    float4 a0 = make_float4(0.f, 0.f, 0.f, 0.f);
    float4 a1 = make_float4(0.f, 0.f, 0.f, 0.f);
    int cur = batch[n0];

    // Pipeline prime: rows n0, n0+1 (clamped)
    const int i1 = (n0 + 1 <= last) ? n0 + 1 : last;
    const float4* rA = reinterpret_cast<const float4*>(feat + (size_t)n0 * CHANNELS) + lane;
    const float4* rB = reinterpret_cast<const float4*>(feat + (size_t)i1 * CHANNELS) + lane;
    float4 fa0 = __ldcs(rA);
    float4 fa1 = __ldcs(rA + 32);
    float4 fb0 = __ldcs(rB);
    float4 fb1 = __ldcs(rB + 32);
    int ga = cur;
    int gb = batch[i1];

    int n = n0;
    // Main loop: process pairs (n, n+1) while prefetching (n+2, n+3)
    for (; n + 1 < n1; n += 2) {
        // ---- prefetch distance 2 (clamped; results discarded past range)
        const int p2 = (n + 2 <= last) ? n + 2 : last;
        const int p3 = (n + 3 <= last) ? n + 3 : last;
        const float4* rP2 = reinterpret_cast<const float4*>(feat + (size_t)p2 * CHANNELS) + lane;
        const float4* rP3 = reinterpret_cast<const float4*>(feat + (size_t)p3 * CHANNELS) + lane;
        float4 na0 = __ldcs(rP2);
        float4 na1 = __ldcs(rP2 + 32);
        float4 nb0 = __ldcs(rP3);
        float4 nb1 = __ldcs(rP3 + 32);
        int nga = batch[p2];
        int ngb = batch[p3];

        // ---- two independent dot products + interleaved butterflies
        float sA = dot8(fa0, fa1, w0, w1);
        float sB = dot8(fb0, fb1, w0, w1);
        #pragma unroll
        for (int o = 16; o > 0; o >>= 1) {
            sA += __shfl_xor_sync(0xFFFFFFFFu, sA, o);
            sB += __shfl_xor_sync(0xFFFFFFFFu, sB, o);
        }
        const float wgtA = __fdividef(1.0f, 1.0f + __expf(-(sA + bias)));
        const float wgtB = __fdividef(1.0f, 1.0f + __expf(-(sB + bias)));

        // ---- accumulate in segment order
        if (ga != cur) {
            flush_seg(out, cur, num_segs, lane, a0, a1);
            a0 = make_float4(0.f, 0.f, 0.f, 0.f);
            a1 = make_float4(0.f, 0.f, 0.f, 0.f);
            cur = ga;
        }
        acc8(a0, a1, fa0, fa1, wgtA);
        if (gb != cur) {
            flush_seg(out, cur, num_segs, lane, a0, a1);
            a0 = make_float4(0.f, 0.f, 0.f, 0.f);
            a1 = make_float4(0.f, 0.f, 0.f, 0.f);
            cur = gb;
        }
        acc8(a0, a1, fb0, fb1, wgtB);

        // ---- shift pipeline
        fa0 = na0; fa1 = na1; fb0 = nb0; fb1 = nb1;
        ga = nga;  gb = ngb;
    }

    // Epilogue: one leftover node (its row is in the A slot)
    if (n < n1) {
        float sA = dot8(fa0, fa1, w0, w1);
        #pragma unroll
        for (int o = 16; o > 0; o >>= 1)
            sA += __shfl_xor_sync(0xFFFFFFFFu, sA, o);
        const float wgtA = __fdividef(1.0f, 1.0f + __expf(-(sA + bias)));
        if (ga != cur) {
            flush_seg(out, cur, num_segs, lane, a0, a1);
            a0 = make_float4(0.f, 0.f, 0.f, 0.f);
            a1 = make_float4(0.f, 0.f, 0.f, 0.f);
            cur = ga;
        }
        acc8(a0, a1, fa0, fa1, wgtA);
    }

    flush_seg(out, cur, num_segs, lane, a0, a1);
}

extern "C" void kernel_launch(void* const* d_in, const int* in_sizes, int n_in,
                              void* d_out, int out_size) {
    const float* feat  = (const float*)d_in[0];  // [N, 256] f32
    const int*   batch = (const int*)d_in[1];    // [N] i32, sorted
    const float* W     = (const float*)d_in[2];  // [256, 1] f32
    const float* b     = (const float*)d_in[3];  // [1] f32
    float*       out   = (float*)d_out;          // [num_segs, 256] f32

    const int N        = in_sizes[1];
    const int num_segs = out_size / CHANNELS;    // 2048

    const int n4 = out_size / 4;
    hgp_zero_kernel<<<(n4 + THREADS - 1) / THREADS, THREADS>>>(
        (float4*)out, n4);

    // 148 SMs * 3 blocks (reg pressure ~80) = one full wave, 24 warps/SM,
    // 4 LDG.128 in flight per warp.
    const int blocks = 444;
    hgp_pool_kernel<<<blocks, THREADS>>>(feat, batch, W, b, out, N, num_segs);
}

// round 5
// speedup vs baseline: 1.2154x; 1.2154x over previous
#include <cuda_runtime.h>
#include <cuda_bf16.h>

// ---------------------------------------------------------------------------
// HyperbolicGraphPooling: out[g] = sum_{n: batch[n]==g} sigmoid(f[n]·W+b) * f[n]
// N=500000, C=256, 2048 graphs, batch int32 sorted ascending.
// R5: R2 structure (regs=64, 32 warps/SM) + zero-register L2 prefetch at
// distance 6. R4 taught us warps > per-warp MLP (regs 83 -> occ 23% -> 119us).
// Target ~78-82 us (LTS cap ~6.5-6.9 TB/s).
// ---------------------------------------------------------------------------

#define CHANNELS 256
#define THREADS  256
#define PF_DIST  6

__global__ void hgp_zero_kernel(float4* __restrict__ out, int n4) {
    int i = blockIdx.x * blockDim.x + threadIdx.x;
    if (i < n4) out[i] = make_float4(0.f, 0.f, 0.f, 0.f);
}

__device__ __forceinline__ void flush_seg(float* __restrict__ out,
                                          int seg, int num_segs, int lane,
                                          const float4& a0, const float4& a1) {
    if (seg < 0 || seg >= num_segs) return;   // defensive
    float* p0 = out + (size_t)seg * CHANNELS + 4 * lane;
    float* p1 = p0 + 128;
    atomicAdd(p0 + 0, a0.x);
    atomicAdd(p0 + 1, a0.y);
    atomicAdd(p0 + 2, a0.z);
    atomicAdd(p0 + 3, a0.w);
    atomicAdd(p1 + 0, a1.x);
    atomicAdd(p1 + 1, a1.y);
    atomicAdd(p1 + 2, a1.z);
    atomicAdd(p1 + 3, a1.w);
}

__global__ __launch_bounds__(THREADS)
void hgp_pool_kernel(const float* __restrict__ feat,
                     const int* __restrict__ batch,
                     const float* __restrict__ W,
                     const float* __restrict__ b,
                     float* __restrict__ out,
                     int N, int num_segs) {
    const int lane        = threadIdx.x & 31;
    const int warp_global = (blockIdx.x * blockDim.x + threadIdx.x) >> 5;
    const int total_warps = (gridDim.x * blockDim.x) >> 5;

    const int per = (N + total_warps - 1) / total_warps;
    const int n0  = warp_global * per;
    const int n1  = (n0 + per < N) ? (n0 + per) : N;
    if (n0 >= n1) return;

    const float4 w0 = *reinterpret_cast<const float4*>(W + 4 * lane);
    const float4 w1 = *reinterpret_cast<const float4*>(W + 128 + 4 * lane);
    const float bias = b[0];

    float4 a0 = make_float4(0.f, 0.f, 0.f, 0.f);
    float4 a1 = make_float4(0.f, 0.f, 0.f, 0.f);
    int cur = batch[n0];

    // Warm L2 for the first few rows of our range (one line per active lane).
    #pragma unroll
    for (int p = 0; p < PF_DIST; ++p) {
        int pn = n0 + p;
        if (pn >= N) pn = N - 1;
        if (lane < 8) {
            const char* pp = reinterpret_cast<const char*>(
                feat + (size_t)pn * CHANNELS) + lane * 128;
            asm volatile("prefetch.global.L2 [%0];" :: "l"(pp));
        }
    }

    // Prime: load row n0
    const float4* row = reinterpret_cast<const float4*>(feat + (size_t)n0 * CHANNELS);
    float4 f0 = row[lane];
    float4 f1 = row[32 + lane];
    int g = cur;

    for (int n = n0; n < n1; ++n) {
        // L2 prefetch for row n+PF_DIST (zero register cost)
        {
            int pn = n + PF_DIST;
            if (pn >= N) pn = N - 1;
            if (lane < 8) {
                const char* pp = reinterpret_cast<const char*>(
                    feat + (size_t)pn * CHANNELS) + lane * 128;
                asm volatile("prefetch.global.L2 [%0];" :: "l"(pp));
            }
        }

        // Architectural prefetch of next row (distance 1, should hit L2)
        float4 nf0, nf1;
        int ng = 0;
        const int np = n + 1;
        if (np < n1) {
            const float4* nrow =
                reinterpret_cast<const float4*>(feat + (size_t)np * CHANNELS);
            nf0 = nrow[lane];
            nf1 = nrow[32 + lane];
            ng  = batch[np];
        }

        // Segment boundary: flush register accumulator
        if (g != cur) {
            flush_seg(out, cur, num_segs, lane, a0, a1);
            a0 = make_float4(0.f, 0.f, 0.f, 0.f);
            a1 = make_float4(0.f, 0.f, 0.f, 0.f);
            cur = g;
        }

        // Per-lane partial dot (8 channels)
        float s = f0.x * w0.x + f0.y * w0.y + f0.z * w0.z + f0.w * w0.w
                + f1.x * w1.x + f1.y * w1.y + f1.z * w1.z + f1.w * w1.w;
        // Full warp reduce
        #pragma unroll
        for (int o = 16; o > 0; o >>= 1)
            s += __shfl_xor_sync(0xFFFFFFFFu, s, o);

        const float wgt = __fdividef(1.0f, 1.0f + __expf(-(s + bias)));

        a0.x += f0.x * wgt; a0.y += f0.y * wgt;
        a0.z += f0.z * wgt; a0.w += f0.w * wgt;
        a1.x += f1.x * wgt; a1.y += f1.y * wgt;
        a1.z += f1.z * wgt; a1.w += f1.w * wgt;

        f0 = nf0; f1 = nf1; g = ng;
    }

    flush_seg(out, cur, num_segs, lane, a0, a1);
}

extern "C" void kernel_launch(void* const* d_in, const int* in_sizes, int n_in,
                              void* d_out, int out_size) {
    const float* feat  = (const float*)d_in[0];  // [N, 256] f32
    const int*   batch = (const int*)d_in[1];    // [N] i32, sorted
    const float* W     = (const float*)d_in[2];  // [256, 1] f32
    const float* b     = (const float*)d_in[3];  // [1] f32
    float*       out   = (float*)d_out;          // [num_segs, 256] f32

    const int N        = in_sizes[1];
    const int num_segs = out_size / CHANNELS;    // 2048

    const int n4 = out_size / 4;
    hgp_zero_kernel<<<(n4 + THREADS - 1) / THREADS, THREADS>>>(
        (float4*)out, n4);

    // 148 SMs * 4 blocks (regs ~64) = 32 warps/SM, one wave, ~106 nodes/warp
    const int blocks = 592;
    hgp_pool_kernel<<<blocks, THREADS>>>(feat, batch, W, b, out, N, num_segs);
}

// round 7
// speedup vs baseline: 1.3716x; 1.1285x over previous
#include <cuda_runtime.h>
#include <cuda_bf16.h>
#include <cstdint>

// ---------------------------------------------------------------------------
// HyperbolicGraphPooling: out[g] = sum_{n: batch[n]==g} sigmoid(f[n]·W+b) * f[n]
// N=500000, C=256, 2048 graphs, batch int32 sorted ascending.
// R7 == R6 + missing <cstdint> (compile fix only).
// cp.async (LDGSTS) 4-stage smem ring per warp -> 4 rows in flight with
// zero register cost. 40 warps/SM via __launch_bounds__(256,5).
// Target ~76-81 us.
// ---------------------------------------------------------------------------

#define CHANNELS 256
#define THREADS  256
#define WARPS    (THREADS / 32)
#define STAGES   4

__global__ void hgp_zero_kernel(float4* __restrict__ out, int n4) {
    int i = blockIdx.x * blockDim.x + threadIdx.x;
    if (i < n4) out[i] = make_float4(0.f, 0.f, 0.f, 0.f);
}

__device__ __forceinline__ void flush_seg(float* __restrict__ out,
                                          int seg, int num_segs, int lane,
                                          const float4& a0, const float4& a1) {
    if (seg < 0 || seg >= num_segs) return;   // defensive
    float* p0 = out + (size_t)seg * CHANNELS + 4 * lane;
    float* p1 = p0 + 128;
    atomicAdd(p0 + 0, a0.x);
    atomicAdd(p0 + 1, a0.y);
    atomicAdd(p0 + 2, a0.z);
    atomicAdd(p0 + 3, a0.w);
    atomicAdd(p1 + 0, a1.x);
    atomicAdd(p1 + 1, a1.y);
    atomicAdd(p1 + 2, a1.z);
    atomicAdd(p1 + 3, a1.w);
}

__device__ __forceinline__ void cp_row(unsigned int s_dst,
                                       const float* __restrict__ feat,
                                       int row, int lane) {
    // Each lane copies its own 32B: channels [4*lane,4*lane+4) and +128.
    const char* g = reinterpret_cast<const char*>(feat + (size_t)row * CHANNELS)
                    + lane * 16;
    asm volatile("cp.async.cg.shared.global [%0], [%1], 16;\n"
                 "cp.async.cg.shared.global [%2], [%3], 16;"
                 :: "r"(s_dst + lane * 16), "l"(g),
                    "r"(s_dst + 512 + lane * 16), "l"(g + 512));
}

__global__ __launch_bounds__(THREADS, 5)
void hgp_pool_kernel(const float* __restrict__ feat,
                     const int* __restrict__ batch,
                     const float* __restrict__ W,
                     const float* __restrict__ b,
                     float* __restrict__ out,
                     int N, int num_segs) {
    __shared__ __align__(16) float ring[WARPS][STAGES][CHANNELS];

    const int lane        = threadIdx.x & 31;
    const int wid         = threadIdx.x >> 5;
    const int warp_global = (blockIdx.x * blockDim.x + threadIdx.x) >> 5;
    const int total_warps = (gridDim.x * blockDim.x) >> 5;

    const int per = (N + total_warps - 1) / total_warps;
    const int n0  = warp_global * per;
    const int n1  = (n0 + per < N) ? (n0 + per) : N;
    if (n0 >= n1) return;

    const unsigned int s_base =
        (unsigned int)__cvta_generic_to_shared(&ring[wid][0][0]);

    const float4 w0 = *reinterpret_cast<const float4*>(W + 4 * lane);
    const float4 w1 = *reinterpret_cast<const float4*>(W + 128 + 4 * lane);
    const float bias = b[0];

    float4 a0 = make_float4(0.f, 0.f, 0.f, 0.f);
    float4 a1 = make_float4(0.f, 0.f, 0.f, 0.f);
    int cur = batch[n0];

    // Prologue: issue rows n0 .. n0+STAGES-2, one commit group per row
    // (empty groups are legal and keep the count uniform).
    #pragma unroll
    for (int p = 0; p < STAGES - 1; ++p) {
        const int pn = n0 + p;
        if (pn < n1)
            cp_row(s_base + ((pn & (STAGES - 1)) << 10), feat, pn, lane);
        asm volatile("cp.async.commit_group;" ::: "memory");
    }

    for (int n = n0; n < n1; ++n) {
        // Issue row n+3 into its slot, commit (possibly empty near the end).
        const int pn = n + STAGES - 1;
        if (pn < n1)
            cp_row(s_base + ((pn & (STAGES - 1)) << 10), feat, pn, lane);
        asm volatile("cp.async.commit_group;" ::: "memory");

        const int g = __ldg(batch + n);

        // Wait until at most 3 newer groups pending => row n's group done.
        asm volatile("cp.async.wait_group 3;" ::: "memory");

        // Each lane reads back exactly the 32B it wrote (no cross-lane smem,
        // so per-thread cp.async visibility suffices; no __syncwarp needed).
        const float* srow = &ring[wid][n & (STAGES - 1)][0];
        const float4 f0 = *reinterpret_cast<const float4*>(srow + 4 * lane);
        const float4 f1 = *reinterpret_cast<const float4*>(srow + 128 + 4 * lane);

        if (g != cur) {
            flush_seg(out, cur, num_segs, lane, a0, a1);
            a0 = make_float4(0.f, 0.f, 0.f, 0.f);
            a1 = make_float4(0.f, 0.f, 0.f, 0.f);
            cur = g;
        }

        float s = f0.x * w0.x + f0.y * w0.y + f0.z * w0.z + f0.w * w0.w
                + f1.x * w1.x + f1.y * w1.y + f1.z * w1.z + f1.w * w1.w;
        #pragma unroll
        for (int o = 16; o > 0; o >>= 1)
            s += __shfl_xor_sync(0xFFFFFFFFu, s, o);

        const float wgt = __fdividef(1.0f, 1.0f + __expf(-(s + bias)));

        a0.x += f0.x * wgt; a0.y += f0.y * wgt;
        a0.z += f0.z * wgt; a0.w += f0.w * wgt;
        a1.x += f1.x * wgt; a1.y += f1.y * wgt;
        a1.z += f1.z * wgt; a1.w += f1.w * wgt;
    }

    flush_seg(out, cur, num_segs, lane, a0, a1);
}

extern "C" void kernel_launch(void* const* d_in, const int* in_sizes, int n_in,
                              void* d_out, int out_size) {
    const float* feat  = (const float*)d_in[0];  // [N, 256] f32
    const int*   batch = (const int*)d_in[1];    // [N] i32, sorted
    const float* W     = (const float*)d_in[2];  // [256, 1] f32
    const float* b     = (const float*)d_in[3];  // [1] f32
    float*       out   = (float*)d_out;          // [num_segs, 256] f32

    const int N        = in_sizes[1];
    const int num_segs = out_size / CHANNELS;    // 2048

    const int n4 = out_size / 4;
    hgp_zero_kernel<<<(n4 + THREADS - 1) / THREADS, THREADS>>>(
        (float4*)out, n4);

    // 148 SMs * 5 blocks * 8 warps = 5920 warps, ~85 nodes each, one wave.
    const int blocks = 740;
    hgp_pool_kernel<<<blocks, THREADS>>>(feat, batch, W, b, out, N, num_segs);
}